// round 6
// baseline (speedup 1.0000x reference)
#include <cuda_runtime.h>
#include <cuda_fp16.h>
#include <cstdint>

#define BB 2
#define HH 16
#define SS 2048
#define DH 128
#define BM 128
#define BN 64
#define NITER 32
#define NSTILE 16
#define NTHREADS 512
#define NSTAGE 4

// smem byte layout
#define QSB 272              // Q/K/V row stride (17*16B, ldmatrix conflict-free)
#define KVST 17408           // one K or V stage: 64*272
#define SM_Q 0               // 128*272 = 34816
#define SM_K 34816           // 4 stages -> 104448
#define SM_V 104448          // 4 stages -> 174080
#define SM_R 174080          // 2*128 floats
#define SM_OST SM_K          // O staging (post-loop), 128*136 floats = 69632
#define SMEM_BYTES 175104

// fp16 K/V scratch, filled by conv_kv kernel
__device__ __half KH[BB * HH * SS * DH];
__device__ __half VH[BB * HH * SS * DH];

__device__ __forceinline__ uint32_t smem_u32(const void* p) {
    uint32_t a;
    asm("{ .reg .u64 t; cvta.to.shared.u64 t, %1; cvt.u32.u64 %0, t; }" : "=r"(a) : "l"(p));
    return a;
}
__device__ __forceinline__ void ldsm_x4(uint32_t& r0, uint32_t& r1, uint32_t& r2, uint32_t& r3, uint32_t a) {
    asm volatile("ldmatrix.sync.aligned.m8n8.x4.shared.b16 {%0,%1,%2,%3}, [%4];"
                 : "=r"(r0), "=r"(r1), "=r"(r2), "=r"(r3) : "r"(a));
}
__device__ __forceinline__ void ldsm_x4t(uint32_t& r0, uint32_t& r1, uint32_t& r2, uint32_t& r3, uint32_t a) {
    asm volatile("ldmatrix.sync.aligned.m8n8.x4.trans.shared.b16 {%0,%1,%2,%3}, [%4];"
                 : "=r"(r0), "=r"(r1), "=r"(r2), "=r"(r3) : "r"(a));
}
__device__ __forceinline__ void mma16816(float* c, uint32_t a0, uint32_t a1, uint32_t a2, uint32_t a3,
                                         uint32_t b0, uint32_t b1) {
    asm volatile(
        "mma.sync.aligned.m16n8k16.row.col.f32.f16.f16.f32 "
        "{%0,%1,%2,%3}, {%4,%5,%6,%7}, {%8,%9}, {%0,%1,%2,%3};"
        : "+f"(c[0]), "+f"(c[1]), "+f"(c[2]), "+f"(c[3])
        : "r"(a0), "r"(a1), "r"(a2), "r"(a3), "r"(b0), "r"(b1));
}
__device__ __forceinline__ void cpa16(uint32_t dst, const void* src) {
    asm volatile("cp.async.cg.shared.global [%0], [%1], 16;" :: "r"(dst), "l"(src) : "memory");
}
#define CPA_COMMIT asm volatile("cp.async.commit_group;" ::: "memory")
#define CPA_WAIT(n) asm volatile("cp.async.wait_group %0;" :: "n"(n) : "memory")

__device__ __forceinline__ uint2 f4h4(float4 v) {
    __half2 a = __floats2half2_rn(v.x, v.y);
    __half2 b = __floats2half2_rn(v.z, v.w);
    uint2 w;
    w.x = *(uint32_t*)&a;
    w.y = *(uint32_t*)&b;
    return w;
}
__device__ __forceinline__ uint32_t packh2(float a, float b) {
    __half2 h = __floats2half2_rn(a, b);
    return *(uint32_t*)&h;
}

// ---- pre-convert K,V fp32 -> fp16 scratch ----
__global__ __launch_bounds__(512, 2)
void conv_kv(const float* __restrict__ k, const float* __restrict__ v) {
    int i = blockIdx.x * blockDim.x + threadIdx.x;
    ((uint2*)KH)[i] = f4h4(((const float4*)k)[i]);
    ((uint2*)VH)[i] = f4h4(((const float4*)v)[i]);
}

__global__ __launch_bounds__(NTHREADS, 1)
void retatt_k6(const float* __restrict__ q, const float* __restrict__ mask,
               float* __restrict__ o)
{
    extern __shared__ char smem[];
    const uint32_t sbase = smem_u32(smem);
    const int tid = threadIdx.x;
    const int wid = tid >> 5;
    const int lane = tid & 31;
    const int g = lane >> 2;
    const int t = lane & 3;
    const int wm = wid >> 1;            // 0..7 : 16-row M strip
    const int wn = wid & 1;             // 0..1 : 32-col K-slice (split-k for GEMM2)
    const int m_base = wm * 16;
    const int n_base = wn * 32;
    const int lrow = lane & 15;
    const int lchunk = (lane >> 4) * 16;

    const int bid = blockIdx.x;
    const int b  = bid & 1;
    const int r_ = bid >> 1;
    const int h  = r_ / NSTILE;
    const int st = r_ % NSTILE;
    const int s0 = st * BM;

    const float* qbase = q + ((size_t)(b * HH + h) * SS + s0) * DH;
    const __half* khb = KH + ((size_t)(b * HH + h) * SS) * DH;
    const __half* vhb = VH + ((size_t)(b * HH + h) * SS) * DH;
    // per-thread mask base: rows (m_base+g, +8), cols n_base+2t (+nt*8, +it*BN)
    const float* mptr = mask + ((size_t)h * SS + s0 + m_base + g) * SS + n_base + 2 * t;

    // ---- prologue: Q fp16 (LDG+cvt+STS); K/V stages 0..2 via cp.async ----
    {
        const float4* gq = (const float4*)qbase;
        #pragma unroll
        for (int i = 0; i < 8; ++i) {
            int f = tid + i * NTHREADS;
            int row = f >> 5, d = (f & 31) << 2;
            *(uint2*)(smem + SM_Q + row * QSB + d * 2) = f4h4(gq[f]);
        }
        #pragma unroll
        for (int s = 0; s < 3; ++s) {
            const uint32_t kd = sbase + SM_K + s * KVST;
            const uint32_t vd = sbase + SM_V + s * KVST;
            #pragma unroll
            for (int i = 0; i < 2; ++i) {
                int f = tid + i * NTHREADS;
                int row = f >> 4, c16 = f & 15;
                cpa16(kd + row * QSB + c16 * 16, khb + (size_t)(s * BN + row) * DH + c16 * 8);
                cpa16(vd + row * QSB + c16 * 16, vhb + (size_t)(s * BN + row) * DH + c16 * 8);
            }
            CPA_COMMIT;
        }
        CPA_WAIT(2);        // stage 0 complete
        __syncthreads();
    }

    float acc2[16][4];
    #pragma unroll
    for (int nt = 0; nt < 16; ++nt)
        #pragma unroll
        for (int i = 0; i < 4; ++i) acc2[nt][i] = 0.f;
    float rsum[2] = {0.f, 0.f};

    const uint32_t qa = sbase + SM_Q + (uint32_t)(m_base + lrow) * QSB + lchunk;

    #pragma unroll 4
    for (int it = 0; it < NITER; ++it) {
        const int stg = it & (NSTAGE - 1);
        const uint32_t sKb = sbase + SM_K + stg * KVST;
        const uint32_t sVb = sbase + SM_V + stg * KVST;

        // ---- mask tile for this iter: direct LDG into regs (consumed in epilogue) ----
        float2 mk0[4], mk1[4];
        {
            const float* mp = mptr + it * BN;
            #pragma unroll
            for (int nt = 0; nt < 4; ++nt) {
                mk0[nt] = *(const float2*)(mp + nt * 8);
                mk1[nt] = *(const float2*)(mp + 8 * SS + nt * 8);
            }
        }

        // ---- prefetch K/V stage it+3 ----
        if (it + 3 < NITER) {
            const int t1 = (it + 3) * BN;
            const int ps = (it + 3) & (NSTAGE - 1);
            const uint32_t kd = sbase + SM_K + ps * KVST;
            const uint32_t vd = sbase + SM_V + ps * KVST;
            #pragma unroll
            for (int i = 0; i < 2; ++i) {
                int f = tid + i * NTHREADS;
                int row = f >> 4, c16 = f & 15;
                cpa16(kd + row * QSB + c16 * 16, khb + (size_t)(t1 + row) * DH + c16 * 8);
                cpa16(vd + row * QSB + c16 * 16, vhb + (size_t)(t1 + row) * DH + c16 * 8);
            }
            CPA_COMMIT;
        }

        // ---- GEMM1: S[16 x 32] per warp = Q @ K^T ----
        float acc1[4][4];
        #pragma unroll
        for (int nt = 0; nt < 4; ++nt)
            #pragma unroll
            for (int i = 0; i < 4; ++i) acc1[nt][i] = 0.f;

        const uint32_t kb0 = sKb + (uint32_t)(n_base + lrow) * QSB + lchunk;
        #pragma unroll
        for (int kk = 0; kk < 8; ++kk) {
            uint32_t a0, a1, a2, a3, b0, b1, b2, b3, c0, c1, c2, c3;
            ldsm_x4(a0, a1, a2, a3, qa + kk * 32);
            ldsm_x4(b0, b1, b2, b3, kb0 + kk * 32);
            ldsm_x4(c0, c1, c2, c3, kb0 + 16 * QSB + kk * 32);
            mma16816(acc1[0], a0, a1, a2, a3, b0, b2);
            mma16816(acc1[1], a0, a1, a2, a3, b1, b3);
            mma16816(acc1[2], a0, a1, a2, a3, c0, c2);
            mma16816(acc1[3], a0, a1, a2, a3, c1, c3);
        }

        // ---- epilogue in registers: P = S*mask, rsum += |P|, pack A-frags ----
        uint32_t A0[4], A1[4];
        {
            uint32_t h01[4], h23[4];
            #pragma unroll
            for (int nt = 0; nt < 4; ++nt) {
                float p0 = acc1[nt][0] * mk0[nt].x;
                float p1 = acc1[nt][1] * mk0[nt].y;
                float p2 = acc1[nt][2] * mk1[nt].x;
                float p3 = acc1[nt][3] * mk1[nt].y;
                rsum[0] += fabsf(p0) + fabsf(p1);
                rsum[1] += fabsf(p2) + fabsf(p3);
                h01[nt] = packh2(p0, p1);
                h23[nt] = packh2(p2, p3);
            }
            A0[0] = h01[0]; A0[1] = h23[0]; A0[2] = h01[1]; A0[3] = h23[1];
            A1[0] = h01[2]; A1[1] = h23[2]; A1[2] = h01[3]; A1[3] = h23[3];
        }

        // ---- GEMM2 (split-k): O_partial += P_slice @ V_slice ----
        #pragma unroll
        for (int kb = 0; kb < 2; ++kb) {
            const uint32_t vrow = sVb + (uint32_t)(n_base + kb * 16 + lrow) * QSB + lchunk;
            #pragma unroll
            for (int dc = 0; dc < 8; ++dc) {
                uint32_t v0, v1, v2, v3;
                ldsm_x4t(v0, v1, v2, v3, vrow + dc * 32);
                if (kb == 0) {
                    mma16816(acc2[2 * dc],     A0[0], A0[1], A0[2], A0[3], v0, v1);
                    mma16816(acc2[2 * dc + 1], A0[0], A0[1], A0[2], A0[3], v2, v3);
                } else {
                    mma16816(acc2[2 * dc],     A1[0], A1[1], A1[2], A1[3], v0, v1);
                    mma16816(acc2[2 * dc + 1], A1[0], A1[1], A1[2], A1[3], v2, v3);
                }
            }
        }

        CPA_WAIT(2);       // stage it+1 complete
        __syncthreads();   // all warps done with stage it; stage it+1 visible
    }

    // ---- r reduction: quad shfl, then across the 2 wn slices via smem ----
    float* sR = (float*)(smem + SM_R);
    #pragma unroll
    for (int half = 0; half < 2; ++half) {
        float vv = rsum[half];
        vv += __shfl_xor_sync(0xffffffffu, vv, 1);
        vv += __shfl_xor_sync(0xffffffffu, vv, 2);
        if (t == 0) sR[wn * BM + m_base + half * 8 + g] = vv;
    }

    // ---- O split-k reduction: wn=0 stages to smem; wn=1 adds + scales + stores ----
    float* ost = (float*)(smem + SM_OST);   // stride 136 floats
    if (wn == 0) {
        #pragma unroll
        for (int nt = 0; nt < 16; ++nt) {
            const int row0 = m_base + g;
            const int cb = nt * 8 + 2 * t;
            *(float2*)&ost[row0 * 136 + cb] = make_float2(acc2[nt][0], acc2[nt][1]);
            *(float2*)&ost[(row0 + 8) * 136 + cb] = make_float2(acc2[nt][2], acc2[nt][3]);
        }
    }
    __syncthreads();

    if (wn == 1) {
        float* ob = o + ((size_t)(b * HH + h) * SS + s0) * DH;
        const int row0 = m_base + g;
        const int row1 = row0 + 8;
        const float inv0 = 1.0f / fmaxf(sR[row0] + sR[BM + row0], 1.0f);
        const float inv1 = 1.0f / fmaxf(sR[row1] + sR[BM + row1], 1.0f);
        #pragma unroll
        for (int nt = 0; nt < 16; ++nt) {
            const int cb = nt * 8 + 2 * t;
            float2 s0v = *(const float2*)&ost[row0 * 136 + cb];
            float2 s1v = *(const float2*)&ost[row1 * 136 + cb];
            *(float2*)&ob[(size_t)row0 * DH + cb] =
                make_float2((s0v.x + acc2[nt][0]) * inv0, (s0v.y + acc2[nt][1]) * inv0);
            *(float2*)&ob[(size_t)row1 * DH + cb] =
                make_float2((s1v.x + acc2[nt][2]) * inv1, (s1v.y + acc2[nt][3]) * inv1);
        }
    }
}

extern "C" void kernel_launch(void* const* d_in, const int* in_sizes, int n_in,
                              void* d_out, int out_size) {
    const float* q = (const float*)d_in[0];
    const float* k = (const float*)d_in[1];
    const float* v = (const float*)d_in[2];
    const float* m = (const float*)d_in[3];
    float* o = (float*)d_out;
    conv_kv<<<(BB * HH * SS * DH / 4) / 512, 512>>>(k, v);
    cudaFuncSetAttribute(retatt_k6,
                         cudaFuncAttributeMaxDynamicSharedMemorySize, SMEM_BYTES);
    retatt_k6<<<BB * HH * NSTILE, NTHREADS, SMEM_BYTES>>>(q, m, o);
}

// round 7
// speedup vs baseline: 1.1209x; 1.1209x over previous
#include <cuda_runtime.h>
#include <cuda_fp16.h>
#include <cstdint>

#define BB 2
#define HH 16
#define SS 2048
#define DH 128
#define BM 128
#define BN 128
#define NITER 16
#define NSTILE 16
#define NTHREADS 512

// smem byte layout
#define QSB 272              // Q/K/V row stride (17*16B, ldmatrix conflict-free)
#define KVST 34816           // one K/V stage: 128*272
#define MSKW 136             // mask row stride in words (544 B, LDS.64 conflict-free)
#define SM_Q 0               // 34816
#define SM_K 34816           // 2 stages -> 104448
#define SM_V 104448          // 1 stage  -> 139264
#define SM_M 139264          // 128*544 = 69632 -> 208896
#define SM_R 208896          // 2*128 floats
#define SM_OST SM_K          // O staging (post-loop): 128*136*4 = 69632 (= both K stages)
#define SMEM_BYTES 209920

// fp16 K/V scratch, filled by conv_kv kernel
__device__ __half KH[BB * HH * SS * DH];
__device__ __half VH[BB * HH * SS * DH];

__device__ __forceinline__ uint32_t smem_u32(const void* p) {
    uint32_t a;
    asm("{ .reg .u64 t; cvta.to.shared.u64 t, %1; cvt.u32.u64 %0, t; }" : "=r"(a) : "l"(p));
    return a;
}
__device__ __forceinline__ void ldsm_x4(uint32_t& r0, uint32_t& r1, uint32_t& r2, uint32_t& r3, uint32_t a) {
    asm volatile("ldmatrix.sync.aligned.m8n8.x4.shared.b16 {%0,%1,%2,%3}, [%4];"
                 : "=r"(r0), "=r"(r1), "=r"(r2), "=r"(r3) : "r"(a));
}
__device__ __forceinline__ void ldsm_x4t(uint32_t& r0, uint32_t& r1, uint32_t& r2, uint32_t& r3, uint32_t a) {
    asm volatile("ldmatrix.sync.aligned.m8n8.x4.trans.shared.b16 {%0,%1,%2,%3}, [%4];"
                 : "=r"(r0), "=r"(r1), "=r"(r2), "=r"(r3) : "r"(a));
}
__device__ __forceinline__ void mma16816(float* c, uint32_t a0, uint32_t a1, uint32_t a2, uint32_t a3,
                                         uint32_t b0, uint32_t b1) {
    asm volatile(
        "mma.sync.aligned.m16n8k16.row.col.f32.f16.f16.f32 "
        "{%0,%1,%2,%3}, {%4,%5,%6,%7}, {%8,%9}, {%0,%1,%2,%3};"
        : "+f"(c[0]), "+f"(c[1]), "+f"(c[2]), "+f"(c[3])
        : "r"(a0), "r"(a1), "r"(a2), "r"(a3), "r"(b0), "r"(b1));
}
__device__ __forceinline__ void cpa16(uint32_t dst, const void* src) {
    asm volatile("cp.async.cg.shared.global [%0], [%1], 16;" :: "r"(dst), "l"(src) : "memory");
}
#define CPA_COMMIT asm volatile("cp.async.commit_group;" ::: "memory")
#define CPA_WAIT(n) asm volatile("cp.async.wait_group %0;" :: "n"(n) : "memory")

__device__ __forceinline__ uint2 f4h4(float4 v) {
    __half2 a = __floats2half2_rn(v.x, v.y);
    __half2 b = __floats2half2_rn(v.z, v.w);
    uint2 w;
    w.x = *(uint32_t*)&a;
    w.y = *(uint32_t*)&b;
    return w;
}
__device__ __forceinline__ uint32_t packh2(float a, float b) {
    __half2 h = __floats2half2_rn(a, b);
    return *(uint32_t*)&h;
}

// ---- pre-convert K,V fp32 -> fp16 scratch ----
__global__ __launch_bounds__(512, 2)
void conv_kv(const float* __restrict__ k, const float* __restrict__ v) {
    int i = blockIdx.x * blockDim.x + threadIdx.x;
    ((uint2*)KH)[i] = f4h4(((const float4*)k)[i]);
    ((uint2*)VH)[i] = f4h4(((const float4*)v)[i]);
}

__global__ __launch_bounds__(NTHREADS, 1)
void retatt_k7(const float* __restrict__ q, const float* __restrict__ mask,
               float* __restrict__ o)
{
    extern __shared__ char smem[];
    const uint32_t sbase = smem_u32(smem);
    const int tid = threadIdx.x;
    const int wid = tid >> 5;
    const int lane = tid & 31;
    const int g = lane >> 2;
    const int t = lane & 3;
    const int wm = wid >> 1;            // 0..7 : 16-row M strip
    const int wn = wid & 1;             // 0..1 : 64-col K-slice (split-k for GEMM2)
    const int m_base = wm * 16;
    const int n_base = wn * 64;
    const int lrow = lane & 15;
    const int lchunk = (lane >> 4) * 16;

    const int bid = blockIdx.x;
    const int b  = bid & 1;
    const int r_ = bid >> 1;
    const int h  = r_ / NSTILE;
    const int st = r_ % NSTILE;
    const int s0 = st * BM;

    const float* qbase = q + ((size_t)(b * HH + h) * SS + s0) * DH;
    const __half* khb = KH + ((size_t)(b * HH + h) * SS) * DH;
    const __half* vhb = VH + ((size_t)(b * HH + h) * SS) * DH;
    const float* mbase = mask + ((size_t)h * SS + s0) * SS;

    // ---- prologue: Q fp16 (LDG+cvt+STS); K0 via cp.async (group A) ----
    {
        const float4* gq = (const float4*)qbase;
        #pragma unroll
        for (int i = 0; i < 8; ++i) {
            int f = tid + i * NTHREADS;
            int row = f >> 5, d = (f & 31) << 2;
            *(uint2*)(smem + SM_Q + row * QSB + d * 2) = f4h4(gq[f]);
        }
        #pragma unroll
        for (int i = 0; i < 4; ++i) {
            int f = tid + i * NTHREADS;
            int row = f >> 4, c16 = f & 15;
            cpa16(sbase + SM_K + row * QSB + c16 * 16, khb + (size_t)row * DH + c16 * 8);
        }
        CPA_COMMIT;
        __syncthreads();     // Q visible to all warps (K handled by wait_group)
    }

    float acc2[16][4];
    #pragma unroll
    for (int nt = 0; nt < 16; ++nt)
        #pragma unroll
        for (int i = 0; i < 4; ++i) acc2[nt][i] = 0.f;
    float rsum[2] = {0.f, 0.f};

    const uint32_t qa = sbase + SM_Q + (uint32_t)(m_base + lrow) * QSB + lchunk;
    const uint32_t sV = sbase + SM_V;

    #pragma unroll 1
    for (int it = 0; it < NITER; ++it) {
        const uint32_t sKb = sbase + SM_K + (it & 1) * KVST;

        // ---- one cp.async group: V(it), mask(it), K(it+1) ----
        {
            #pragma unroll
            for (int i = 0; i < 4; ++i) {           // V(it): 128 rows x 8 chunks
                int f = tid + i * NTHREADS;
                int row = f >> 4, c16 = f & 15;
                cpa16(sV + row * QSB + c16 * 16, vhb + (size_t)(it * BN + row) * DH + c16 * 8);
            }
            #pragma unroll
            for (int i = 0; i < 8; ++i) {           // mask(it): 128 rows x 32 chunks (fp32)
                int f = tid + i * NTHREADS;
                int row = f >> 5, c16 = f & 31;
                cpa16(sbase + SM_M + row * (MSKW * 4) + c16 * 16,
                      mbase + (size_t)row * SS + it * BN + c16 * 4);
            }
            if (it + 1 < NITER) {                   // K(it+1)
                const uint32_t kd = sbase + SM_K + ((it + 1) & 1) * KVST;
                #pragma unroll
                for (int i = 0; i < 4; ++i) {
                    int f = tid + i * NTHREADS;
                    int row = f >> 4, c16 = f & 15;
                    cpa16(kd + row * QSB + c16 * 16,
                          khb + (size_t)((it + 1) * BN + row) * DH + c16 * 8);
                }
            }
            CPA_COMMIT;
        }

        CPA_WAIT(1);         // K(it) (previous group) complete
        if (it == 0) __syncthreads();   // K0 visibility for all warps

        // ---- GEMM1: S[16 x 64] per warp = Q @ K_slice^T ----
        float acc1[8][4];
        #pragma unroll
        for (int nt = 0; nt < 8; ++nt)
            #pragma unroll
            for (int i = 0; i < 4; ++i) acc1[nt][i] = 0.f;

        const uint32_t kb0 = sKb + (uint32_t)(n_base + lrow) * QSB + lchunk;
        #pragma unroll
        for (int kk = 0; kk < 8; ++kk) {
            uint32_t a0, a1, a2, a3;
            ldsm_x4(a0, a1, a2, a3, qa + kk * 32);
            #pragma unroll
            for (int j = 0; j < 4; ++j) {
                uint32_t b0, b1, b2, b3;
                ldsm_x4(b0, b1, b2, b3, kb0 + j * 16 * QSB + kk * 32);
                mma16816(acc1[2 * j],     a0, a1, a2, a3, b0, b2);
                mma16816(acc1[2 * j + 1], a0, a1, a2, a3, b1, b3);
            }
        }

        CPA_WAIT(0);         // V(it), mask(it) complete
        __syncthreads();     // all warps done reading K(it-1 stage about to be... ) + mask/V visible

        // ---- epilogue in registers: P = S*mask, rsum += |P|, pack A-frags ----
        uint32_t A[4][4];    // A[kb] = GEMM2 A-fragment for k-block kb
        {
            const uint32_t mrow0 = sbase + SM_M + (uint32_t)(m_base + g) * (MSKW * 4)
                                 + (uint32_t)(n_base + 2 * t) * 4;
            #pragma unroll
            for (int nt = 0; nt < 8; ++nt) {
                float2 m0 = *(const float2*)(smem + (mrow0 - sbase) + nt * 32);
                float2 m1 = *(const float2*)(smem + (mrow0 - sbase) + 8 * (MSKW * 4) + nt * 32);
                float p0 = acc1[nt][0] * m0.x;
                float p1 = acc1[nt][1] * m0.y;
                float p2 = acc1[nt][2] * m1.x;
                float p3 = acc1[nt][3] * m1.y;
                rsum[0] += fabsf(p0) + fabsf(p1);
                rsum[1] += fabsf(p2) + fabsf(p3);
                A[nt >> 1][(nt & 1) ? 2 : 0] = packh2(p0, p1);
                A[nt >> 1][(nt & 1) ? 3 : 1] = packh2(p2, p3);
            }
        }

        // ---- GEMM2 (split-k): O_partial += P_slice @ V_slice ----
        #pragma unroll
        for (int kb = 0; kb < 4; ++kb) {
            const uint32_t vrow = sV + (uint32_t)(n_base + kb * 16 + lrow) * QSB + lchunk;
            #pragma unroll
            for (int dc = 0; dc < 8; ++dc) {
                uint32_t v0, v1, v2, v3;
                ldsm_x4t(v0, v1, v2, v3, vrow + dc * 32);
                mma16816(acc2[2 * dc],     A[kb][0], A[kb][1], A[kb][2], A[kb][3], v0, v1);
                mma16816(acc2[2 * dc + 1], A[kb][0], A[kb][1], A[kb][2], A[kb][3], v2, v3);
            }
        }

        __syncthreads();     // all warps done with V(it)/mask(it) before next overwrite
    }

    // ---- r reduction: quad shfl, then across the 2 wn slices via smem ----
    float* sR = (float*)(smem + SM_R);
    #pragma unroll
    for (int half = 0; half < 2; ++half) {
        float vv = rsum[half];
        vv += __shfl_xor_sync(0xffffffffu, vv, 1);
        vv += __shfl_xor_sync(0xffffffffu, vv, 2);
        if (t == 0) sR[wn * BM + m_base + half * 8 + g] = vv;
    }

    // ---- O split-k reduction: wn=0 stages to smem; wn=1 adds + scales + stores ----
    float* ost = (float*)(smem + SM_OST);   // stride 136 floats
    if (wn == 0) {
        #pragma unroll
        for (int nt = 0; nt < 16; ++nt) {
            const int row0 = m_base + g;
            const int cb = nt * 8 + 2 * t;
            *(float2*)&ost[row0 * 136 + cb] = make_float2(acc2[nt][0], acc2[nt][1]);
            *(float2*)&ost[(row0 + 8) * 136 + cb] = make_float2(acc2[nt][2], acc2[nt][3]);
        }
    }
    __syncthreads();

    if (wn == 1) {
        float* ob = o + ((size_t)(b * HH + h) * SS + s0) * DH;
        const int row0 = m_base + g;
        const int row1 = row0 + 8;
        const float inv0 = 1.0f / fmaxf(sR[row0] + sR[BM + row0], 1.0f);
        const float inv1 = 1.0f / fmaxf(sR[row1] + sR[BM + row1], 1.0f);
        #pragma unroll
        for (int nt = 0; nt < 16; ++nt) {
            const int cb = nt * 8 + 2 * t;
            float2 s0v = *(const float2*)&ost[row0 * 136 + cb];
            float2 s1v = *(const float2*)&ost[row1 * 136 + cb];
            *(float2*)&ob[(size_t)row0 * DH + cb] =
                make_float2((s0v.x + acc2[nt][0]) * inv0, (s0v.y + acc2[nt][1]) * inv0);
            *(float2*)&ob[(size_t)row1 * DH + cb] =
                make_float2((s1v.x + acc2[nt][2]) * inv1, (s1v.y + acc2[nt][3]) * inv1);
        }
    }
}

extern "C" void kernel_launch(void* const* d_in, const int* in_sizes, int n_in,
                              void* d_out, int out_size) {
    const float* q = (const float*)d_in[0];
    const float* k = (const float*)d_in[1];
    const float* v = (const float*)d_in[2];
    const float* m = (const float*)d_in[3];
    float* o = (float*)d_out;
    conv_kv<<<(BB * HH * SS * DH / 4) / 512, 512>>>(k, v);
    cudaFuncSetAttribute(retatt_k7,
                         cudaFuncAttributeMaxDynamicSharedMemorySize, SMEM_BYTES);
    retatt_k7<<<BB * HH * NSTILE, NTHREADS, SMEM_BYTES>>>(q, m, o);
}

// round 8
// speedup vs baseline: 1.1806x; 1.0533x over previous
#include <cuda_runtime.h>
#include <cuda_fp16.h>
#include <cstdint>

#define BB 2
#define HH 16
#define SS 2048
#define DH 128
#define BM 128
#define BN 128
#define NITER 16
#define NSTILE 16
#define NTHREADS 512

// smem byte layout
#define QSB 272              // Q/K/V row stride (17*16B, ldmatrix conflict-free)
#define KVST 34816           // one K/V stage: 128*272
#define MSKW 136             // mask row stride in words (544 B)
#define SM_Q 0               // 34816
#define SM_K 34816           // 2 stages -> 104448
#define SM_V 104448          // 1 stage  -> 139264
#define SM_M 139264          // 128*544 = 69632 -> 208896
#define SM_R 208896          // 2*128 floats
#define SM_OST SM_K          // O staging (post-loop)
#define SMEM_BYTES 209920

// fp16 K/V scratch, filled by conv_kv kernel
__device__ __half KH[BB * HH * SS * DH];
__device__ __half VH[BB * HH * SS * DH];

__device__ __forceinline__ uint32_t smem_u32(const void* p) {
    uint32_t a;
    asm("{ .reg .u64 t; cvta.to.shared.u64 t, %1; cvt.u32.u64 %0, t; }" : "=r"(a) : "l"(p));
    return a;
}
__device__ __forceinline__ void ldsm_x4(uint32_t& r0, uint32_t& r1, uint32_t& r2, uint32_t& r3, uint32_t a) {
    asm volatile("ldmatrix.sync.aligned.m8n8.x4.shared.b16 {%0,%1,%2,%3}, [%4];"
                 : "=r"(r0), "=r"(r1), "=r"(r2), "=r"(r3) : "r"(a));
}
__device__ __forceinline__ void ldsm_x4t(uint32_t& r0, uint32_t& r1, uint32_t& r2, uint32_t& r3, uint32_t a) {
    asm volatile("ldmatrix.sync.aligned.m8n8.x4.trans.shared.b16 {%0,%1,%2,%3}, [%4];"
                 : "=r"(r0), "=r"(r1), "=r"(r2), "=r"(r3) : "r"(a));
}
__device__ __forceinline__ void mma16816(float* c, uint32_t a0, uint32_t a1, uint32_t a2, uint32_t a3,
                                         uint32_t b0, uint32_t b1) {
    asm volatile(
        "mma.sync.aligned.m16n8k16.row.col.f32.f16.f16.f32 "
        "{%0,%1,%2,%3}, {%4,%5,%6,%7}, {%8,%9}, {%0,%1,%2,%3};"
        : "+f"(c[0]), "+f"(c[1]), "+f"(c[2]), "+f"(c[3])
        : "r"(a0), "r"(a1), "r"(a2), "r"(a3), "r"(b0), "r"(b1));
}
__device__ __forceinline__ void cpa16(uint32_t dst, const void* src) {
    asm volatile("cp.async.cg.shared.global [%0], [%1], 16;" :: "r"(dst), "l"(src) : "memory");
}
#define CPA_COMMIT asm volatile("cp.async.commit_group;" ::: "memory")
#define CPA_WAIT(n) asm volatile("cp.async.wait_group %0;" :: "n"(n) : "memory")
// per-group barrier: group wn uses named barrier wn+1, 256 threads (8 warps)
#define GBAR asm volatile("bar.sync %0, 256;" :: "r"(wn + 1) : "memory")

__device__ __forceinline__ uint2 f4h4(float4 v) {
    __half2 a = __floats2half2_rn(v.x, v.y);
    __half2 b = __floats2half2_rn(v.z, v.w);
    uint2 w;
    w.x = *(uint32_t*)&a;
    w.y = *(uint32_t*)&b;
    return w;
}
__device__ __forceinline__ uint32_t packh2(float a, float b) {
    __half2 h = __floats2half2_rn(a, b);
    return *(uint32_t*)&h;
}

// ---- pre-convert K,V fp32 -> fp16 scratch ----
__global__ __launch_bounds__(512, 2)
void conv_kv(const float* __restrict__ k, const float* __restrict__ v) {
    int i = blockIdx.x * blockDim.x + threadIdx.x;
    ((uint2*)KH)[i] = f4h4(((const float4*)k)[i]);
    ((uint2*)VH)[i] = f4h4(((const float4*)v)[i]);
}

__global__ __launch_bounds__(NTHREADS, 1)
void retatt_k8(const float* __restrict__ q, const float* __restrict__ mask,
               float* __restrict__ o)
{
    extern __shared__ char smem[];
    const uint32_t sbase = smem_u32(smem);
    const int tid = threadIdx.x;
    const int wid = tid >> 5;
    const int lane = tid & 31;
    const int g = lane >> 2;
    const int t = lane & 3;
    const int wm = wid >> 1;            // 0..7 : 16-row M strip
    const int wn = wid & 1;             // 0..1 : 64-col K-slice group
    const int m_base = wm * 16;
    const int n_base = wn * 64;
    const int lrow = lane & 15;
    const int lchunk = (lane >> 4) * 16;
    const int gt = wm * 32 + lane;      // thread id within the 256-thread group

    const int bid = blockIdx.x;
    const int b  = bid & 1;
    const int r_ = bid >> 1;
    const int h  = r_ / NSTILE;
    const int st = r_ % NSTILE;
    const int s0 = st * BM;

    const float* qbase = q + ((size_t)(b * HH + h) * SS + s0) * DH;
    const __half* khb = KH + ((size_t)(b * HH + h) * SS) * DH;
    const __half* vhb = VH + ((size_t)(b * HH + h) * SS) * DH;
    const float* mbase = mask + ((size_t)h * SS + s0) * SS;

    // ---- prologue: Q fp16 (all threads); K0 group-half via cp.async ----
    {
        const float4* gq = (const float4*)qbase;
        #pragma unroll
        for (int i = 0; i < 8; ++i) {
            int f = tid + i * NTHREADS;
            int row = f >> 5, d = (f & 31) << 2;
            *(uint2*)(smem + SM_Q + row * QSB + d * 2) = f4h4(gq[f]);
        }
        #pragma unroll
        for (int i = 0; i < 4; ++i) {   // K0 rows [n_base, n_base+64)
            int f = gt + i * 256;
            int lr = f >> 4, c16 = f & 15;
            cpa16(sbase + SM_K + (n_base + lr) * QSB + c16 * 16,
                  khb + (size_t)(n_base + lr) * DH + c16 * 8);
        }
        CPA_COMMIT;
        __syncthreads();                // Q visible to all
    }

    float acc2[16][4];
    #pragma unroll
    for (int nt = 0; nt < 16; ++nt)
        #pragma unroll
        for (int i = 0; i < 4; ++i) acc2[nt][i] = 0.f;
    float rsum[2] = {0.f, 0.f};

    const uint32_t qa = sbase + SM_Q + (uint32_t)(m_base + lrow) * QSB + lchunk;
    const uint32_t sV = sbase + SM_V;

    #pragma unroll 1
    for (int it = 0; it < NITER; ++it) {
        const uint32_t sKb = sbase + SM_K + (it & 1) * KVST;

        // ---- group-owned cp.async: V(it) half, mask(it) cols, K(it+1) half ----
        {
            #pragma unroll
            for (int i = 0; i < 4; ++i) {           // V(it) rows [n_base, +64)
                int f = gt + i * 256;
                int lr = f >> 4, c16 = f & 15;
                cpa16(sV + (n_base + lr) * QSB + c16 * 16,
                      vhb + (size_t)(it * BN + n_base + lr) * DH + c16 * 8);
            }
            #pragma unroll
            for (int i = 0; i < 8; ++i) {           // mask(it) cols [n_base, +64), all 128 rows
                int f = gt + i * 256;
                int row = f >> 4, c16 = f & 15;
                cpa16(sbase + SM_M + row * (MSKW * 4) + n_base * 4 + c16 * 16,
                      mbase + (size_t)row * SS + it * BN + n_base + c16 * 4);
            }
            if (it + 1 < NITER) {                   // K(it+1) rows [n_base, +64)
                const uint32_t kd = sbase + SM_K + ((it + 1) & 1) * KVST;
                #pragma unroll
                for (int i = 0; i < 4; ++i) {
                    int f = gt + i * 256;
                    int lr = f >> 4, c16 = f & 15;
                    cpa16(kd + (n_base + lr) * QSB + c16 * 16,
                          khb + (size_t)((it + 1) * BN + n_base + lr) * DH + c16 * 8);
                }
            }
            CPA_COMMIT;
        }

        CPA_WAIT(1);                    // this group's K(it) complete
        if (it == 0) GBAR;              // K0 visibility within group

        // ---- GEMM1: S[16 x 64] per warp = Q @ K_slice^T ----
        float acc1[8][4];
        #pragma unroll
        for (int nt = 0; nt < 8; ++nt)
            #pragma unroll
            for (int i = 0; i < 4; ++i) acc1[nt][i] = 0.f;

        const uint32_t kb0 = sKb + (uint32_t)(n_base + lrow) * QSB + lchunk;
        #pragma unroll
        for (int kk = 0; kk < 8; ++kk) {
            uint32_t a0, a1, a2, a3;
            ldsm_x4(a0, a1, a2, a3, qa + kk * 32);
            #pragma unroll
            for (int j = 0; j < 4; ++j) {
                uint32_t b0, b1, b2, b3;
                ldsm_x4(b0, b1, b2, b3, kb0 + j * 16 * QSB + kk * 32);
                mma16816(acc1[2 * j],     a0, a1, a2, a3, b0, b2);
                mma16816(acc1[2 * j + 1], a0, a1, a2, a3, b1, b3);
            }
        }

        CPA_WAIT(0);                    // this group's V(it), mask(it) complete
        GBAR;                           // group-wide visibility of V/mask

        // ---- epilogue in registers: P = S*mask, rsum += |P|, pack A-frags ----
        uint32_t A[4][4];
        {
            const uint32_t moff = SM_M + (uint32_t)(m_base + g) * (MSKW * 4)
                                + (uint32_t)(n_base + 2 * t) * 4;
            #pragma unroll
            for (int nt = 0; nt < 8; ++nt) {
                float2 m0 = *(const float2*)(smem + moff + nt * 32);
                float2 m1 = *(const float2*)(smem + moff + 8 * (MSKW * 4) + nt * 32);
                float p0 = acc1[nt][0] * m0.x;
                float p1 = acc1[nt][1] * m0.y;
                float p2 = acc1[nt][2] * m1.x;
                float p3 = acc1[nt][3] * m1.y;
                rsum[0] += fabsf(p0) + fabsf(p1);
                rsum[1] += fabsf(p2) + fabsf(p3);
                A[nt >> 1][(nt & 1) ? 2 : 0] = packh2(p0, p1);
                A[nt >> 1][(nt & 1) ? 3 : 1] = packh2(p2, p3);
            }
        }

        // ---- GEMM2 (split-k): O_partial += P_slice @ V_slice ----
        #pragma unroll
        for (int kb = 0; kb < 4; ++kb) {
            const uint32_t vrow = sV + (uint32_t)(n_base + kb * 16 + lrow) * QSB + lchunk;
            #pragma unroll
            for (int dc = 0; dc < 8; ++dc) {
                uint32_t v0, v1, v2, v3;
                ldsm_x4t(v0, v1, v2, v3, vrow + dc * 32);
                mma16816(acc2[2 * dc],     A[kb][0], A[kb][1], A[kb][2], A[kb][3], v0, v1);
                mma16816(acc2[2 * dc + 1], A[kb][0], A[kb][1], A[kb][2], A[kb][3], v2, v3);
            }
        }

        GBAR;                           // group done with V(it)/mask(it) before next writes
    }

    __syncthreads();                    // re-converge both groups

    // ---- r reduction: quad shfl, then across the 2 wn slices via smem ----
    float* sR = (float*)(smem + SM_R);
    #pragma unroll
    for (int half = 0; half < 2; ++half) {
        float vv = rsum[half];
        vv += __shfl_xor_sync(0xffffffffu, vv, 1);
        vv += __shfl_xor_sync(0xffffffffu, vv, 2);
        if (t == 0) sR[wn * BM + m_base + half * 8 + g] = vv;
    }

    // ---- O split-k reduction: wn=0 stages to smem; wn=1 adds + scales + stores ----
    float* ost = (float*)(smem + SM_OST);   // stride 136 floats
    if (wn == 0) {
        #pragma unroll
        for (int nt = 0; nt < 16; ++nt) {
            const int row0 = m_base + g;
            const int cb = nt * 8 + 2 * t;
            *(float2*)&ost[row0 * 136 + cb] = make_float2(acc2[nt][0], acc2[nt][1]);
            *(float2*)&ost[(row0 + 8) * 136 + cb] = make_float2(acc2[nt][2], acc2[nt][3]);
        }
    }
    __syncthreads();

    if (wn == 1) {
        float* ob = o + ((size_t)(b * HH + h) * SS + s0) * DH;
        const int row0 = m_base + g;
        const int row1 = row0 + 8;
        const float inv0 = 1.0f / fmaxf(sR[row0] + sR[BM + row0], 1.0f);
        const float inv1 = 1.0f / fmaxf(sR[row1] + sR[BM + row1], 1.0f);
        #pragma unroll
        for (int nt = 0; nt < 16; ++nt) {
            const int cb = nt * 8 + 2 * t;
            float2 s0v = *(const float2*)&ost[row0 * 136 + cb];
            float2 s1v = *(const float2*)&ost[row1 * 136 + cb];
            *(float2*)&ob[(size_t)row0 * DH + cb] =
                make_float2((s0v.x + acc2[nt][0]) * inv0, (s0v.y + acc2[nt][1]) * inv0);
            *(float2*)&ob[(size_t)row1 * DH + cb] =
                make_float2((s1v.x + acc2[nt][2]) * inv1, (s1v.y + acc2[nt][3]) * inv1);
        }
    }
}

extern "C" void kernel_launch(void* const* d_in, const int* in_sizes, int n_in,
                              void* d_out, int out_size) {
    const float* q = (const float*)d_in[0];
    const float* k = (const float*)d_in[1];
    const float* v = (const float*)d_in[2];
    const float* m = (const float*)d_in[3];
    float* o = (float*)d_out;
    conv_kv<<<(BB * HH * SS * DH / 4) / 512, 512>>>(k, v);
    cudaFuncSetAttribute(retatt_k8,
                         cudaFuncAttributeMaxDynamicSharedMemorySize, SMEM_BYTES);
    retatt_k8<<<BB * HH * NSTILE, NTHREADS, SMEM_BYTES>>>(q, m, o);
}